// round 12
// baseline (speedup 1.0000x reference)
#include <cuda_runtime.h>
#include <cstdint>

// GaussianPooling: out[n,c] = sum_{dy,dx} fm[c, y+dy, x+dx] * kern[dy,dx]
// fm: [512,256,256] f32, keypoints: [4096,2] int (x,y), out: [4096,512] f32.
// Separable 5x5 Gaussian (sigma=2).
//
// prep: 256 blocks (16 stripes x 16 keypoint-slices) bin keypoints into
//       per-(stripe,part) queues; early PDL trigger.
// main: block = (16-row stripe, group of 8 channels) = 4 channel-pair tiles,
//       processed with DOUBLE-BUFFERED cp.async.bulk: tile t+1 streams into
//       the spare buffer while tile t is vconv'd (SMEM->SMEM in place) and
//       gathered (2 LDS.128 per kp per channel, STG.64 out).

#define C_DIM 512
#define H_DIM 256
#define W_DIM 256
#define N_KP  4096
#define PLANE (H_DIM * W_DIM)
#define STRIPE_ROWS 16
#define N_STRIPES (H_DIM / STRIPE_ROWS)          // 16
#define N_PARTS 16
#define PART_KP (N_KP / N_PARTS)                 // 256
#define RAW_ROWS 20                              // 16 + 2 halo each side
#define STR 260                                  // row stride floats (1040B)
#define CH_OFF (RAW_ROWS * STR)                  // 5200 floats per channel
#define CG 2                                     // channels per tile
#define BUF_FLOATS (CG * CH_OFF)                 // 10400
#define SMEM_BYTES (2 * BUF_FLOATS * 4)          // 83200 (double buffer)
#define TX_BYTES (CG * RAW_ROWS * W_DIM * 4)     // 40960
#define TPB 4                                    // tiles (channel pairs)/block
#define N_CGRP (C_DIM / (CG * TPB))              // 64 channel groups

__device__ int g_q[N_STRIPES * N_PARTS * PART_KP];  // packed (n<<16)|(x<<8)|y
__device__ int g_qcnt[N_STRIPES * N_PARTS];

static __device__ __forceinline__ float gval(float i) {
    float d = i - 2.0f;
    return __expf(-d * d * 0.125f);              // exp(-d^2/(2*sigma^2))
}

static __device__ __forceinline__ uint32_t smem_u32(const void* p) {
    return (uint32_t)__cvta_generic_to_shared(p);
}

// grid = 16 stripes x 16 parts. Each block scans its 256-keypoint slice for
// its stripe. dtype detect per slice: words kp32[2n+1] are y (int32 case,
// random nonzero somewhere in slice) or int64 high halves (all zero).
__global__ void prep_kp_kernel(const int* __restrict__ kp32)
{
    __shared__ int s_or[256];
    __shared__ int s_flag;
    __shared__ int s_cnt;
    const int t      = threadIdx.x;
    const int stripe = blockIdx.x >> 4;
    const int part   = blockIdx.x & (N_PARTS - 1);
    const int n      = part * PART_KP + t;

    s_or[t] = kp32[2 * n + 1];
    if (t == 0) s_cnt = 0;
    __syncthreads();
    for (int s = 128; s > 0; s >>= 1) {
        if (t < s) s_or[t] |= s_or[t + s];
        __syncthreads();
    }
    if (t == 0) s_flag = s_or[0];
    __syncthreads();
    const bool is_i32 = (s_flag != 0);

    int x, y;
    if (is_i32) { x = kp32[2 * n];     y = kp32[2 * n + 1]; }
    else        { x = kp32[4 * n];     y = kp32[4 * n + 2]; }
    x = min(max(x, 2), W_DIM - 3);
    y = min(max(y, 2), H_DIM - 3);

    if ((y >> 4) == stripe) {
        int idx = atomicAdd(&s_cnt, 1);
        g_q[(stripe * N_PARTS + part) * PART_KP + idx] =
            (n << 16) | (x << 8) | y;
    }
    __syncthreads();
    if (t == 0) g_qcnt[stripe * N_PARTS + part] = s_cnt;

    cudaTriggerProgrammaticLaunchCompletion();
}

__global__ void __launch_bounds__(256)
gauss_pool_kernel(const float* __restrict__ fm, float* __restrict__ out)
{
    extern __shared__ float s_buf[];             // [2][BUF_FLOATS]
    __shared__ __align__(16) float s_gx[4][8];
    __shared__ __align__(8)  unsigned long long s_mbar[TPB];

    const int cgrp   = blockIdx.x & (N_CGRP - 1);
    const int stripe = blockIdx.x >> 6;
    const int t      = threadIdx.x;
    const int row0   = stripe * STRIPE_ROWS - 2;

    if (t < TPB) {
        asm volatile("mbarrier.init.shared.b64 [%0], %1;"
                     :: "r"(smem_u32(&s_mbar[t])), "r"(1u) : "memory");
    }

    const float inv_norm =
        1.0f / (gval(0.f) + gval(1.f) + gval(2.f) + gval(3.f) + gval(4.f));

    if (t < 32) {
        int off = t >> 3, j = t & 7;
        int i = j - off;
        s_gx[off][j] = (i >= 0 && i < 5) ? gval((float)i) * inv_norm : 0.0f;
    }
    const float g0 = gval(0.f) * inv_norm;
    const float g1 = gval(1.f) * inv_norm;
    const float g2 = gval(2.f) * inv_norm;

    __syncthreads();                             // mbarriers + s_gx ready

    // --- TMA bulk-copy issue for tile `tile` into buffer tile&1 ---
    auto issue_load = [&](int tile) {
        const uint32_t mb = smem_u32(&s_mbar[tile]);
        if (t == 0) {
            asm volatile("mbarrier.arrive.expect_tx.shared.b64 _, [%0], %1;"
                         :: "r"(mb), "r"((uint32_t)TX_BYTES) : "memory");
        }
        if (t < CG * RAW_ROWS) {                 // 40 x 1KB row copies
            const int ch  = t / RAW_ROWS;
            const int row = t - ch * RAW_ROWS;
            const int gr  = min(max(row0 + row, 0), H_DIM - 1); // legal addr;
            // clamped rows are never read (keypoint y clipped to [2,253])
            const int c   = cgrp * (CG * TPB) + tile * CG + ch;
            const float* src = fm + (size_t)c * PLANE + gr * W_DIM;
            const uint32_t dst = smem_u32(s_buf)
                + (uint32_t)((tile & 1) * BUF_FLOATS + ch * CH_OFF + row * STR) * 4u;
            asm volatile(
                "cp.async.bulk.shared::cta.global.mbarrier::complete_tx::bytes "
                "[%0], [%1], %2, [%3];"
                :: "r"(dst), "l"(src), "r"((uint32_t)(W_DIM * 4)), "r"(mb)
                : "memory");
        }
    };

    issue_load(0);
    cudaGridDependencySynchronize();             // kp queues ready (PDL)

    const int warp = t >> 5;
    const int lane = t & 31;
    const int strip = t & 63;                    // vconv float4 column
    const int vb    = (t >> 6) * 4;              // vconv first V row (0..12)

    #pragma unroll 1
    for (int tile = 0; tile < TPB; ++tile) {
        if (tile + 1 < TPB) issue_load(tile + 1);   // prefetch next tile

        // wait for this tile's data (parity 0; acquire orders LDS)
        {
            const uint32_t mb = smem_u32(&s_mbar[tile]);
            uint32_t done;
            asm volatile(
                "{\n\t.reg .pred p;\n\t"
                "mbarrier.try_wait.parity.acquire.cta.shared::cta.b64 p, [%1], %2;\n\t"
                "selp.b32 %0, 1, 0, p;\n\t}"
                : "=r"(done) : "r"(mb), "r"(0u) : "memory");
            if (!done) {
                asm volatile(
                    "{\n\t.reg .pred P1;\n\t"
                    "W_%=:\n\t"
                    "mbarrier.try_wait.parity.acquire.cta.shared::cta.b64 P1, [%0], %1, 0x989680;\n\t"
                    "@P1 bra.uni D_%=;\n\t"
                    "bra.uni W_%=;\n\t"
                    "D_%=:\n\t}"
                    :: "r"(mb), "r"(0u) : "memory");
            }
        }

        float* bufp = s_buf + (tile & 1) * BUF_FLOATS;

        // ---- vertical conv SMEM->SMEM in place, per channel ----
        // V row vi (overwrites raw row vi) = conv(raw vi..vi+4); thread
        // stages raw rows vb..vb+7 then writes V rows vb..vb+3 after sync.
        #pragma unroll
        for (int ch = 0; ch < CG; ++ch) {
            float* tp = bufp + ch * CH_OFF;
            float4 w[8];
            #pragma unroll
            for (int k = 0; k < 8; ++k)
                w[k] = *(const float4*)&tp[(vb + k) * STR + strip * 4];
            __syncthreads();                     // all stages before writes
            #pragma unroll
            for (int j = 0; j < 4; ++j) {
                float4 r;
                r.x = g0 * (w[j].x + w[j+4].x) + g1 * (w[j+1].x + w[j+3].x) + g2 * w[j+2].x;
                r.y = g0 * (w[j].y + w[j+4].y) + g1 * (w[j+1].y + w[j+3].y) + g2 * w[j+2].y;
                r.z = g0 * (w[j].z + w[j+4].z) + g1 * (w[j+1].z + w[j+3].z) + g2 * w[j+2].z;
                r.w = g0 * (w[j].w + w[j+4].w) + g1 * (w[j+1].w + w[j+3].w) + g2 * w[j+2].w;
                *(float4*)&tp[(vb + j) * STR + strip * 4] = r;
            }
        }
        __syncthreads();                         // V writes visible to gather

        // ---- gather: one warp per part (16 parts, 8 warps x 2) ----
        const int c0 = cgrp * (CG * TPB) + tile * CG;
        #pragma unroll 1
        for (int pp = 0; pp < N_PARTS / 8; ++pp) {
            const int p   = warp + pp * 8;
            const int qi  = stripe * N_PARTS + p;
            const int cnt = g_qcnt[qi];
            const int* q  = &g_q[qi * PART_KP];

            for (int i = lane; i < cnt; i += 32) {
                const int v = q[i];
                const int y = v & 255;
                const int x = (v >> 8) & 255;
                const int n = v >> 16;

                const int w0c = x - 2;
                const int a   = w0c & ~3;
                const int off = w0c - a;
                const int yl  = y - stripe * STRIPE_ROWS;   // 0..15

                float4 G0 = *(const float4*)&s_gx[off][0];
                float4 G1 = *(const float4*)&s_gx[off][4];

                const float* b0 = bufp + yl * STR + a;
                const float* b1 = b0 + CH_OFF;

                float4 A = *(const float4*)(b0);
                float4 B = *(const float4*)(b0 + 4);
                float4 C = *(const float4*)(b1);
                float4 D = *(const float4*)(b1 + 4);

                float2 res;
                res.x = G0.x * A.x + G0.y * A.y + G0.z * A.z + G0.w * A.w
                      + G1.x * B.x + G1.y * B.y + G1.z * B.z + G1.w * B.w;
                res.y = G0.x * C.x + G0.y * C.y + G0.z * C.z + G0.w * C.w
                      + G1.x * D.x + G1.y * D.y + G1.z * D.z + G1.w * D.w;

                *(float2*)&out[n * C_DIM + c0] = res;
            }
        }
        __syncthreads();                         // buffer free for tile+2
    }
}

extern "C" void kernel_launch(void* const* d_in, const int* in_sizes, int n_in,
                              void* d_out, int out_size)
{
    const float* fm   = (const float*)d_in[0];
    const int*   kp32 = (const int*)d_in[1];
    float*       out  = (float*)d_out;

    cudaFuncSetAttribute(gauss_pool_kernel,
                         cudaFuncAttributeMaxDynamicSharedMemorySize,
                         SMEM_BYTES);

    prep_kp_kernel<<<N_STRIPES * N_PARTS, 256>>>(kp32);

    cudaLaunchConfig_t cfg = {};
    cfg.gridDim  = dim3(N_STRIPES * N_CGRP);
    cfg.blockDim = dim3(256);
    cfg.dynamicSmemBytes = SMEM_BYTES;
    cfg.stream = 0;
    cudaLaunchAttribute attr[1];
    attr[0].id = cudaLaunchAttributeProgrammaticStreamSerialization;
    attr[0].val.programmaticStreamSerializationAllowed = 1;
    cfg.attrs = attr;
    cfg.numAttrs = 1;
    cudaLaunchKernelEx(&cfg, gauss_pool_kernel, fm, out);
}

// round 13
// speedup vs baseline: 1.3001x; 1.3001x over previous
#include <cuda_runtime.h>
#include <cstdint>

// GaussianPooling: out[n,c] = sum_{dy,dx} fm[c, y+dy, x+dx] * kern[dy,dx]
// fm: [512,256,256] f32, keypoints: [4096,2] int (x,y), out: [4096,512] f32.
// Separable 5x5 Gaussian (sigma=2).
//
// R11 (best main) + phase-stagger: co-resident blocks offset their TMA fetch
// start by (bid%3)*2us in the first wave, de-phase-locking fetch vs compute
// across blocks so DRAM stays busy through the whole kernel.

#define C_DIM 512
#define H_DIM 256
#define W_DIM 256
#define N_KP  4096
#define PLANE (H_DIM * W_DIM)
#define STRIPE_ROWS 32
#define N_STRIPES (H_DIM / STRIPE_ROWS)          // 8
#define N_PARTS 16
#define PART_KP (N_KP / N_PARTS)                 // 256
#define RAW_ROWS 36                              // 32 + 2 halo each side
#define STR 260                                  // row stride floats (1040B)
#define CH_OFF (RAW_ROWS * STR)                  // 9360 floats per channel
#define CG 2
#define SMEM_BYTES (CG * CH_OFF * 4)             // 74880
#define TX_BYTES (CG * RAW_ROWS * W_DIM * 4)     // 73728
#define FIRSTWAVE 444                            // 148 SMs x 3 blocks/SM
#define STAGGER_NS 2000ULL

__device__ int g_q[N_STRIPES * N_PARTS * PART_KP];  // packed (n<<16)|(x<<8)|y
__device__ int g_qcnt[N_STRIPES * N_PARTS];

static __device__ __forceinline__ float gval(float i) {
    float d = i - 2.0f;
    return __expf(-d * d * 0.125f);              // exp(-d^2/(2*sigma^2))
}

static __device__ __forceinline__ uint32_t smem_u32(const void* p) {
    return (uint32_t)__cvta_generic_to_shared(p);
}

static __device__ __forceinline__ unsigned long long gtimer() {
    unsigned long long v;
    asm volatile("mov.u64 %0, %%globaltimer;" : "=l"(v));
    return v;
}

// grid = 8 stripes x 16 parts. Each block scans its 256-keypoint slice for
// its stripe. dtype detect per slice: words kp32[2n+1] are y (int32 case,
// random nonzero somewhere in slice) or int64 high halves (all zero).
__global__ void prep_kp_kernel(const int* __restrict__ kp32)
{
    __shared__ int s_or[256];
    __shared__ int s_flag;
    __shared__ int s_cnt;
    const int t      = threadIdx.x;
    const int stripe = blockIdx.x >> 4;
    const int part   = blockIdx.x & (N_PARTS - 1);
    const int n      = part * PART_KP + t;

    s_or[t] = kp32[2 * n + 1];
    if (t == 0) s_cnt = 0;
    __syncthreads();
    for (int s = 128; s > 0; s >>= 1) {
        if (t < s) s_or[t] |= s_or[t + s];
        __syncthreads();
    }
    if (t == 0) s_flag = s_or[0];
    __syncthreads();
    const bool is_i32 = (s_flag != 0);

    int x, y;
    if (is_i32) { x = kp32[2 * n];     y = kp32[2 * n + 1]; }
    else        { x = kp32[4 * n];     y = kp32[4 * n + 2]; }
    x = min(max(x, 2), W_DIM - 3);
    y = min(max(y, 2), H_DIM - 3);

    if ((y >> 5) == stripe) {
        int idx = atomicAdd(&s_cnt, 1);
        g_q[(stripe * N_PARTS + part) * PART_KP + idx] =
            (n << 16) | (x << 8) | y;
    }
    __syncthreads();
    if (t == 0) g_qcnt[stripe * N_PARTS + part] = s_cnt;

    cudaTriggerProgrammaticLaunchCompletion();
}

__global__ void __launch_bounds__(256, 3)
gauss_pool_kernel(const float* __restrict__ fm, float* __restrict__ out)
{
    extern __shared__ float s_v[];               // raw then in-place V tiles
    __shared__ __align__(16) float s_gx[4][8];
    __shared__ __align__(8)  unsigned long long s_mbar;

    const int cg0    = (blockIdx.x & 255) * CG;
    const int stripe = blockIdx.x >> 8;
    const int t      = threadIdx.x;
    const int row0   = stripe * STRIPE_ROWS - 2;

    const uint32_t mbar = smem_u32(&s_mbar);

    if (t == 0) {
        asm volatile("mbarrier.init.shared.b64 [%0], %1;"
                     :: "r"(mbar), "r"(1u) : "memory");
    }

    // ---- phase stagger: de-phase-lock co-resident blocks' fetch bursts ----
    // Co-resident blocks are bid, bid+148, bid+296 -> (bid%3) distinct.
    if (t == 0 && blockIdx.x < FIRSTWAVE) {
        const unsigned long long delay =
            (unsigned long long)(blockIdx.x % 3) * STAGGER_NS;
        if (delay) {
            const unsigned long long tgt = gtimer() + delay;
            int guard = 0;
            while (gtimer() < tgt && ++guard < 1000000) __nanosleep(128);
        }
    }
    __syncthreads();                             // mbar init + stagger done

    if (t == 0) {
        asm volatile("mbarrier.arrive.expect_tx.shared.b64 _, [%0], %1;"
                     :: "r"(mbar), "r"((uint32_t)TX_BYTES) : "memory");
    }
    // 72 bulk copies: 2 channels x 36 rows, 1KB each (TMA engine).
    if (t < CG * RAW_ROWS) {
        const int ch  = t / RAW_ROWS;
        const int row = t - ch * RAW_ROWS;
        const int gr  = min(max(row0 + row, 0), H_DIM - 1);  // legal addr;
        // clamped rows are never read (keypoint y is clipped to [2,253])
        const float* src = fm + (size_t)(cg0 + ch) * PLANE + gr * W_DIM;
        const uint32_t dst =
            smem_u32(s_v) + (uint32_t)(ch * CH_OFF + row * STR) * 4u;
        asm volatile(
            "cp.async.bulk.shared::cta.global.mbarrier::complete_tx::bytes "
            "[%0], [%1], %2, [%3];"
            :: "r"(dst), "l"(src), "r"((uint32_t)(W_DIM * 4)), "r"(mbar)
            : "memory");
    }

    const float inv_norm =
        1.0f / (gval(0.f) + gval(1.f) + gval(2.f) + gval(3.f) + gval(4.f));

    if (t < 32) {
        int off = t >> 3, j = t & 7;
        int i = j - off;
        s_gx[off][j] = (i >= 0 && i < 5) ? gval((float)i) * inv_norm : 0.0f;
    }

    const float g0 = gval(0.f) * inv_norm;
    const float g1 = gval(1.f) * inv_norm;
    const float g2 = gval(2.f) * inv_norm;

    // wait for the raw tile (parity 0; acquire orders subsequent LDS)
    {
        uint32_t done;
        asm volatile(
            "{\n\t.reg .pred p;\n\t"
            "mbarrier.try_wait.parity.acquire.cta.shared::cta.b64 p, [%1], %2;\n\t"
            "selp.b32 %0, 1, 0, p;\n\t}"
            : "=r"(done) : "r"(mbar), "r"(0u) : "memory");
        if (!done) {
            asm volatile(
                "{\n\t.reg .pred P1;\n\t"
                "W_%=:\n\t"
                "mbarrier.try_wait.parity.acquire.cta.shared::cta.b64 P1, [%0], %1, 0x989680;\n\t"
                "@P1 bra.uni D_%=;\n\t"
                "bra.uni W_%=;\n\t"
                "D_%=:\n\t}"
                :: "r"(mbar), "r"(0u) : "memory");
        }
    }

    // ---- Phase 1b: vertical conv SMEM->SMEM, in place ----
    // V row vi (overwrites raw row vi) = conv of raw rows vi..vi+4.
    // Two 16-row halves per channel; stage 8 raw rows to registers, sync,
    // then write 4 V rows per thread.
    {
        const int strip = t & 63;                // float4 column
        const int chunk = t >> 6;                // 0..3

        #pragma unroll
        for (int cg = 0; cg < CG; ++cg) {
            float* tile = s_v + cg * CH_OFF;
            #pragma unroll
            for (int half = 0; half < 2; ++half) {
                const int vb = half * 16 + chunk * 4;   // first V row
                float4 w[8];
                #pragma unroll
                for (int k = 0; k < 8; ++k)
                    w[k] = *(const float4*)&tile[(vb + k) * STR + strip * 4];
                __syncthreads();                 // all stages before writes
                #pragma unroll
                for (int j = 0; j < 4; ++j) {
                    float4 r;
                    r.x = g0 * (w[j].x + w[j+4].x) + g1 * (w[j+1].x + w[j+3].x) + g2 * w[j+2].x;
                    r.y = g0 * (w[j].y + w[j+4].y) + g1 * (w[j+1].y + w[j+3].y) + g2 * w[j+2].y;
                    r.z = g0 * (w[j].z + w[j+4].z) + g1 * (w[j+1].z + w[j+3].z) + g2 * w[j+2].z;
                    r.w = g0 * (w[j].w + w[j+4].w) + g1 * (w[j+1].w + w[j+3].w) + g2 * w[j+2].w;
                    *(float4*)&tile[(vb + j) * STR + strip * 4] = r;
                }
                __syncthreads();                 // writes before next stage
            }
        }
    }

    cudaGridDependencySynchronize();             // queues ready (PDL)

    // ---- Phase 2: one warp per part (16 parts, 8 warps x 2 rounds) ----
    const int warp = t >> 5;
    const int lane = t & 31;

    #pragma unroll 1
    for (int pp = 0; pp < N_PARTS / 8; ++pp) {
        const int p   = warp + pp * 8;
        const int qi  = stripe * N_PARTS + p;
        const int cnt = g_qcnt[qi];
        const int* q  = &g_q[qi * PART_KP];

        for (int i = lane; i < cnt; i += 32) {
            const int v = q[i];
            const int y = v & 255;
            const int x = (v >> 8) & 255;
            const int n = v >> 16;

            const int w0c = x - 2;
            const int a   = w0c & ~3;
            const int off = w0c - a;
            const int yl  = y - stripe * STRIPE_ROWS;   // 0..31

            float4 G0 = *(const float4*)&s_gx[off][0];
            float4 G1 = *(const float4*)&s_gx[off][4];

            const float* b0 = s_v + yl * STR + a;
            const float* b1 = b0 + CH_OFF;

            float4 A = *(const float4*)(b0);
            float4 B = *(const float4*)(b0 + 4);
            float4 C = *(const float4*)(b1);
            float4 D = *(const float4*)(b1 + 4);

            float2 res;
            res.x = G0.x * A.x + G0.y * A.y + G0.z * A.z + G0.w * A.w
                  + G1.x * B.x + G1.y * B.y + G1.z * B.z + G1.w * B.w;
            res.y = G0.x * C.x + G0.y * C.y + G0.z * C.z + G0.w * C.w
                  + G1.x * D.x + G1.y * D.y + G1.z * D.z + G1.w * D.w;

            *(float2*)&out[n * C_DIM + cg0] = res;
        }
    }
}

extern "C" void kernel_launch(void* const* d_in, const int* in_sizes, int n_in,
                              void* d_out, int out_size)
{
    const float* fm   = (const float*)d_in[0];
    const int*   kp32 = (const int*)d_in[1];
    float*       out  = (float*)d_out;

    cudaFuncSetAttribute(gauss_pool_kernel,
                         cudaFuncAttributeMaxDynamicSharedMemorySize,
                         SMEM_BYTES);

    prep_kp_kernel<<<N_STRIPES * N_PARTS, 256>>>(kp32);

    cudaLaunchConfig_t cfg = {};
    cfg.gridDim  = dim3(N_STRIPES * (C_DIM / CG));
    cfg.blockDim = dim3(256);
    cfg.dynamicSmemBytes = SMEM_BYTES;
    cfg.stream = 0;
    cudaLaunchAttribute attr[1];
    attr[0].id = cudaLaunchAttributeProgrammaticStreamSerialization;
    attr[0].val.programmaticStreamSerializationAllowed = 1;
    cfg.attrs = attr;
    cfg.numAttrs = 1;
    cudaLaunchKernelEx(&cfg, gauss_pool_kernel, fm, out);
}